// round 2
// baseline (speedup 1.0000x reference)
#include <cuda_runtime.h>
#include <cstdint>

#define L_Q 8192
#define D_MODEL 2048
#define S_CTX 512
#define D_CTX 4096
#define N_HEADS 16
#define D_HEAD 128

// Scratch (allocation-free rule: __device__ globals, referenced directly
// from device code — no cudaGetSymbolAddress in the capture path)
__device__ float g_qbuf[(size_t)L_Q * D_MODEL];
__device__ float g_kbuf[(size_t)S_CTX * D_MODEL];
__device__ float g_vbuf[(size_t)S_CTX * D_MODEL];
__device__ float g_abuf[(size_t)L_Q * D_MODEL];

__device__ __forceinline__ uint32_t f2tf(float f) {
  uint32_t u; asm("cvt.rna.tf32.f32 %0, %1;" : "=r"(u) : "f"(f)); return u;
}

__device__ __forceinline__ void mma_tf32(float c[4], const uint32_t a[4], const uint32_t b[2]) {
  asm("mma.sync.aligned.m16n8k8.row.col.f32.tf32.tf32.f32 "
      "{%0,%1,%2,%3}, {%4,%5,%6,%7}, {%8,%9}, {%0,%1,%2,%3};"
      : "+f"(c[0]), "+f"(c[1]), "+f"(c[2]), "+f"(c[3])
      : "r"(a[0]), "r"(a[1]), "r"(a[2]), "r"(a[3]), "r"(b[0]), "r"(b[1]));
}

// ---------------------------------------------------------------------------
// GEMM: C[M,N] = A[M,K] @ B[K,N] + bias.  Block tile 128x128, K-chunk 32,
// 256 threads, warp tile 64x32 (warps 2m x 4n).  A,B staged in smem as tf32
// bit patterns (converted once at store).  Register prefetch of next chunk.
// Requires M%128==0, N%128==0, K%32==0 (true for all uses here).
// ---------------------------------------------------------------------------
__device__ __forceinline__ void gemm_body(
    const float* __restrict__ A, const float* __restrict__ B,
    const float* __restrict__ bias, float* __restrict__ C,
    int M, int N, int K, int bm, int bn)
{
  __shared__ uint32_t As[128 * 36];   // [m][k], ld 36 (36%32==4 -> conflict-free A frags)
  __shared__ uint32_t Bs[32 * 136];   // [k][n], ld 136 (136%32==8 -> conflict-free B frags)

  const int tid = threadIdx.x;
  const int lane = tid & 31, warp = tid >> 5;
  const int g = lane >> 2, tig = lane & 3;
  const int wm = (warp >> 2) * 64, wn = (warp & 3) * 32;
  const int m0 = bm * 128, n0 = bn * 128;

  float acc[4][4][4];
  #pragma unroll
  for (int mi = 0; mi < 4; mi++)
    #pragma unroll
    for (int ni = 0; ni < 4; ni++)
      #pragma unroll
      for (int e = 0; e < 4; e++) acc[mi][ni][e] = 0.f;

  const int nk = K >> 5;
  float4 pa[4], pb[4];

  // prologue: load chunk 0
  #pragma unroll
  for (int i = 0; i < 4; i++) {
    int idx = tid + i * 256;
    pa[i] = *(const float4*)&A[(size_t)(m0 + (idx >> 3)) * K + ((idx & 7) << 2)];
    pb[i] = *(const float4*)&B[(size_t)(idx >> 5) * N + n0 + ((idx & 31) << 2)];
  }
  #pragma unroll
  for (int i = 0; i < 4; i++) {
    int idx = tid + i * 256;
    *(uint4*)&As[(idx >> 3) * 36 + ((idx & 7) << 2)] =
        make_uint4(f2tf(pa[i].x), f2tf(pa[i].y), f2tf(pa[i].z), f2tf(pa[i].w));
    *(uint4*)&Bs[(idx >> 5) * 136 + ((idx & 31) << 2)] =
        make_uint4(f2tf(pb[i].x), f2tf(pb[i].y), f2tf(pb[i].z), f2tf(pb[i].w));
  }
  __syncthreads();

  #pragma unroll 1
  for (int kc = 0; kc < nk; kc++) {
    if (kc + 1 < nk) {
      int ko = (kc + 1) << 5;
      #pragma unroll
      for (int i = 0; i < 4; i++) {
        int idx = tid + i * 256;
        pa[i] = *(const float4*)&A[(size_t)(m0 + (idx >> 3)) * K + ko + ((idx & 7) << 2)];
        pb[i] = *(const float4*)&B[(size_t)(ko + (idx >> 5)) * N + n0 + ((idx & 31) << 2)];
      }
    }
    #pragma unroll
    for (int ks = 0; ks < 4; ks++) {
      uint32_t af[4][4], bf[4][2];
      #pragma unroll
      for (int mi = 0; mi < 4; mi++) {
        int base = (wm + mi * 16 + g) * 36 + ks * 8 + tig;
        af[mi][0] = As[base];
        af[mi][1] = As[base + 8 * 36];
        af[mi][2] = As[base + 4];
        af[mi][3] = As[base + 8 * 36 + 4];
      }
      #pragma unroll
      for (int ni = 0; ni < 4; ni++) {
        int col = wn + ni * 8 + g;
        bf[ni][0] = Bs[(ks * 8 + tig) * 136 + col];
        bf[ni][1] = Bs[(ks * 8 + tig + 4) * 136 + col];
      }
      #pragma unroll
      for (int mi = 0; mi < 4; mi++)
        #pragma unroll
        for (int ni = 0; ni < 4; ni++)
          mma_tf32(acc[mi][ni], af[mi], bf[ni]);
    }
    __syncthreads();
    if (kc + 1 < nk) {
      #pragma unroll
      for (int i = 0; i < 4; i++) {
        int idx = tid + i * 256;
        *(uint4*)&As[(idx >> 3) * 36 + ((idx & 7) << 2)] =
            make_uint4(f2tf(pa[i].x), f2tf(pa[i].y), f2tf(pa[i].z), f2tf(pa[i].w));
        *(uint4*)&Bs[(idx >> 5) * 136 + ((idx & 31) << 2)] =
            make_uint4(f2tf(pb[i].x), f2tf(pb[i].y), f2tf(pb[i].z), f2tf(pb[i].w));
      }
      __syncthreads();
    }
  }

  // epilogue: +bias, write fp32
  #pragma unroll
  for (int mi = 0; mi < 4; mi++) {
    int r = m0 + wm + mi * 16 + g;
    #pragma unroll
    for (int ni = 0; ni < 4; ni++) {
      int c = n0 + wn + ni * 8 + 2 * tig;
      float b0 = bias[c], b1 = bias[c + 1];
      *(float2*)&C[(size_t)r * N + c] =
          make_float2(acc[mi][ni][0] + b0, acc[mi][ni][1] + b1);
      *(float2*)&C[(size_t)(r + 8) * N + c] =
          make_float2(acc[mi][ni][2] + b0, acc[mi][ni][3] + b1);
    }
  }
}

// Q projection: writes the g_qbuf scratch (direct device-symbol reference)
__global__ __launch_bounds__(256, 1) void gemm_q_k(
    const float* __restrict__ A, const float* __restrict__ B,
    const float* __restrict__ bias)
{
  gemm_body(A, B, bias, g_qbuf, L_Q, D_MODEL, D_MODEL, blockIdx.y, blockIdx.x);
}

// O projection: reads g_abuf scratch, writes harness output
__global__ __launch_bounds__(256, 1) void gemm_o_k(
    const float* __restrict__ B, const float* __restrict__ bias,
    float* __restrict__ C)
{
  gemm_body(g_abuf, B, bias, C, L_Q, D_MODEL, D_MODEL, blockIdx.y, blockIdx.x);
}

// K,V projections fused over blockIdx.z
__global__ __launch_bounds__(256, 1) void gemm_kv_k(
    const float* __restrict__ A,
    const float* __restrict__ Bk, const float* __restrict__ bk,
    const float* __restrict__ Bv, const float* __restrict__ bv)
{
  const float* B  = blockIdx.z ? Bv : Bk;
  const float* bb = blockIdx.z ? bv : bk;
  float*       C  = blockIdx.z ? g_vbuf : g_kbuf;
  gemm_body(A, B, bb, C, S_CTX, D_MODEL, D_CTX, blockIdx.y, blockIdx.x);
}

// ---------------------------------------------------------------------------
// RMSNorm in place over rows of 2048, one block per row.  which=0 -> g_qbuf,
// which=1 -> g_kbuf.
// ---------------------------------------------------------------------------
__global__ __launch_bounds__(256, 1) void rmsnorm_k(int which,
                                                    const float* __restrict__ gw)
{
  float* data = which ? g_kbuf : g_qbuf;
  const int row = blockIdx.x, tid = threadIdx.x;
  const int lane = tid & 31, warp = tid >> 5;
  float4* p = (float4*)(data + (size_t)row * D_MODEL);
  float4 v0 = p[tid], v1 = p[tid + 256];
  float s = v0.x * v0.x + v0.y * v0.y + v0.z * v0.z + v0.w * v0.w
          + v1.x * v1.x + v1.y * v1.y + v1.z * v1.z + v1.w * v1.w;
  #pragma unroll
  for (int o = 16; o; o >>= 1) s += __shfl_xor_sync(0xffffffffu, s, o);
  __shared__ float ws[8];
  if (lane == 0) ws[warp] = s;
  __syncthreads();
  float tot = ws[0] + ws[1] + ws[2] + ws[3] + ws[4] + ws[5] + ws[6] + ws[7];
  float scl = rsqrtf(tot * (1.0f / D_MODEL) + 1e-6f);
  const float4* gp = (const float4*)gw;
  float4 g0 = gp[tid], g1 = gp[tid + 256];
  v0.x *= scl * g0.x; v0.y *= scl * g0.y; v0.z *= scl * g0.z; v0.w *= scl * g0.w;
  v1.x *= scl * g1.x; v1.y *= scl * g1.y; v1.z *= scl * g1.z; v1.w *= scl * g1.w;
  p[tid] = v0; p[tid + 256] = v1;
}

// ---------------------------------------------------------------------------
// Attention: one block = (head, 64 q rows).  Materialize 64x512 scores in
// smem via tf32 MMA, smem softmax (unnormalized; 1/sum folded into PV
// epilogue), then P @ V via tf32 MMA.  256 threads.
// Smem: qs 64x132 (tf32 bits) | kvs 64x136 (tf32 bits, K then V chunks)
//       | sc 64x516 fp32 | rinv 64 fp32  -> 200,960 B dynamic.
// ---------------------------------------------------------------------------
#define ATTN_SMEM_BYTES ((64 * 132 + 64 * 136 + 64 * 516 + 64) * 4)

__global__ __launch_bounds__(256, 1) void attn_k()
{
  extern __shared__ uint32_t sm[];
  uint32_t* qs  = sm;                     // [64][132]  (132%32==4)
  uint32_t* kvs = sm + 64 * 132;          // [64][132] as K / [64][136] as V
  float*    sc  = (float*)(sm + 64 * 132 + 64 * 136);  // [64][516] (516%32==4)
  float*    rinv = sc + 64 * 516;         // [64]

  const float* __restrict__ q  = g_qbuf;
  const float* __restrict__ kk = g_kbuf;
  const float* __restrict__ vv = g_vbuf;
  float* __restrict__ o = g_abuf;

  const int tid = threadIdx.x;
  const int lane = tid & 31, warp = tid >> 5;
  const int g = lane >> 2, tig = lane & 3;
  const int h = blockIdx.y;
  const int qb = blockIdx.x * 64;
  const size_t hoff = (size_t)h * D_HEAD;

  // Load Q tile (convert to tf32 bits at store)
  #pragma unroll
  for (int i = 0; i < 8; i++) {
    int idx = tid + i * 256;
    int row = idx >> 5, c4 = (idx & 31) << 2;
    float4 vq = *(const float4*)&q[(size_t)(qb + row) * D_MODEL + hoff + c4];
    uint32_t* d = &qs[row * 132 + c4];
    d[0] = f2tf(vq.x); d[1] = f2tf(vq.y); d[2] = f2tf(vq.z); d[3] = f2tf(vq.w);
  }

  // ---- Phase A: scores = Q K^T (raw, fp32 in smem) ----
  const int wmA = (warp >> 2) * 32, wnA = (warp & 3) * 16;
  #pragma unroll 1
  for (int st = 0; st < 8; st++) {
    __syncthreads();
    #pragma unroll
    for (int i = 0; i < 8; i++) {
      int idx = tid + i * 256;
      int row = idx >> 5, c4 = (idx & 31) << 2;
      float4 vk = *(const float4*)&kk[(size_t)(st * 64 + row) * D_MODEL + hoff + c4];
      uint32_t* d = &kvs[row * 132 + c4];
      d[0] = f2tf(vk.x); d[1] = f2tf(vk.y); d[2] = f2tf(vk.z); d[3] = f2tf(vk.w);
    }
    __syncthreads();

    float acc[2][2][4];
    #pragma unroll
    for (int mi = 0; mi < 2; mi++)
      #pragma unroll
      for (int ni = 0; ni < 2; ni++)
        #pragma unroll
        for (int e = 0; e < 4; e++) acc[mi][ni][e] = 0.f;

    #pragma unroll
    for (int ks = 0; ks < 16; ks++) {
      uint32_t af[2][4], bf[2][2];
      #pragma unroll
      for (int mi = 0; mi < 2; mi++) {
        int base = (wmA + mi * 16 + g) * 132 + ks * 8 + tig;
        af[mi][0] = qs[base];
        af[mi][1] = qs[base + 8 * 132];
        af[mi][2] = qs[base + 4];
        af[mi][3] = qs[base + 8 * 132 + 4];
      }
      #pragma unroll
      for (int ni = 0; ni < 2; ni++) {
        int col = wnA + ni * 8 + g;          // s index
        bf[ni][0] = kvs[col * 132 + ks * 8 + tig];
        bf[ni][1] = kvs[col * 132 + ks * 8 + tig + 4];
      }
      #pragma unroll
      for (int mi = 0; mi < 2; mi++)
        #pragma unroll
        for (int ni = 0; ni < 2; ni++)
          mma_tf32(acc[mi][ni], af[mi], bf[ni]);
    }
    #pragma unroll
    for (int mi = 0; mi < 2; mi++) {
      int r = wmA + mi * 16 + g;
      #pragma unroll
      for (int ni = 0; ni < 2; ni++) {
        int c = st * 64 + wnA + ni * 8 + 2 * tig;
        *(float2*)&sc[r * 516 + c]       = make_float2(acc[mi][ni][0], acc[mi][ni][1]);
        *(float2*)&sc[(r + 8) * 516 + c] = make_float2(acc[mi][ni][2], acc[mi][ni][3]);
      }
    }
  }
  __syncthreads();

  // ---- Softmax (store unnormalized probs as tf32 bits; keep 1/sum) ----
  const float sscale = 0.08838834764831845f;  // 1/sqrt(128)
  #pragma unroll 1
  for (int j = 0; j < 8; j++) {
    int r = warp * 8 + j;
    float* row = &sc[r * 516];
    float mx = -1e30f;
    #pragma unroll
    for (int c = lane; c < 512; c += 32) mx = fmaxf(mx, row[c]);
    #pragma unroll
    for (int off = 16; off; off >>= 1) mx = fmaxf(mx, __shfl_xor_sync(0xffffffffu, mx, off));
    float sum = 0.f;
    #pragma unroll
    for (int c = lane; c < 512; c += 32) {
      float e = __expf((row[c] - mx) * sscale);
      sum += e;
      row[c] = __uint_as_float(f2tf(e));
    }
    #pragma unroll
    for (int off = 16; off; off >>= 1) sum += __shfl_xor_sync(0xffffffffu, sum, off);
    if (lane == 0) rinv[r] = 1.0f / sum;
  }
  __syncthreads();

  // ---- Phase B: out = P @ V ----
  const int wmB = (warp >> 2) * 32, wnB = (warp & 3) * 32;
  float co[2][4][4];
  #pragma unroll
  for (int mi = 0; mi < 2; mi++)
    #pragma unroll
    for (int ni = 0; ni < 4; ni++)
      #pragma unroll
      for (int e = 0; e < 4; e++) co[mi][ni][e] = 0.f;

  #pragma unroll 1
  for (int sv = 0; sv < 8; sv++) {
    __syncthreads();
    #pragma unroll
    for (int i = 0; i < 8; i++) {
      int idx = tid + i * 256;
      int row = idx >> 5, c4 = (idx & 31) << 2;
      float4 vw = *(const float4*)&vv[(size_t)(sv * 64 + row) * D_MODEL + hoff + c4];
      uint32_t* d = &kvs[row * 136 + c4];
      d[0] = f2tf(vw.x); d[1] = f2tf(vw.y); d[2] = f2tf(vw.z); d[3] = f2tf(vw.w);
    }
    __syncthreads();

    #pragma unroll
    for (int ks = 0; ks < 8; ks++) {
      uint32_t af[2][4], bf[4][2];
      #pragma unroll
      for (int mi = 0; mi < 2; mi++) {
        int base = (wmB + mi * 16 + g) * 516 + sv * 64 + ks * 8 + tig;
        af[mi][0] = __float_as_uint(sc[base]);
        af[mi][1] = __float_as_uint(sc[base + 8 * 516]);
        af[mi][2] = __float_as_uint(sc[base + 4]);
        af[mi][3] = __float_as_uint(sc[base + 8 * 516 + 4]);
      }
      #pragma unroll
      for (int ni = 0; ni < 4; ni++) {
        int col = wnB + ni * 8 + g;          // d index
        bf[ni][0] = kvs[(ks * 8 + tig) * 136 + col];
        bf[ni][1] = kvs[(ks * 8 + tig + 4) * 136 + col];
      }
      #pragma unroll
      for (int mi = 0; mi < 2; mi++)
        #pragma unroll
        for (int ni = 0; ni < 4; ni++)
          mma_tf32(co[mi][ni], af[mi], bf[ni]);
    }
  }

  // epilogue: normalize by 1/sum, write to attn buffer
  #pragma unroll
  for (int mi = 0; mi < 2; mi++) {
    int rl = wmB + mi * 16 + g;
    float r0 = rinv[rl], r1 = rinv[rl + 8];
    #pragma unroll
    for (int ni = 0; ni < 4; ni++) {
      int c = wnB + ni * 8 + 2 * tig;
      *(float2*)&o[(size_t)(qb + rl) * D_MODEL + hoff + c] =
          make_float2(co[mi][ni][0] * r0, co[mi][ni][1] * r0);
      *(float2*)&o[(size_t)(qb + rl + 8) * D_MODEL + hoff + c] =
          make_float2(co[mi][ni][2] * r1, co[mi][ni][3] * r1);
    }
  }
}

// ---------------------------------------------------------------------------
extern "C" void kernel_launch(void* const* d_in, const int* in_sizes, int n_in,
                              void* d_out, int out_size)
{
  const float* x   = (const float*)d_in[0];
  const float* ctx = (const float*)d_in[1];
  const float* Wq  = (const float*)d_in[2];
  const float* bq  = (const float*)d_in[3];
  const float* Wk  = (const float*)d_in[4];
  const float* bk  = (const float*)d_in[5];
  const float* Wv  = (const float*)d_in[6];
  const float* bv  = (const float*)d_in[7];
  const float* Wo  = (const float*)d_in[8];
  const float* bo  = (const float*)d_in[9];
  const float* gq  = (const float*)d_in[10];
  const float* gk  = (const float*)d_in[11];
  float* out = (float*)d_out;

  cudaFuncSetAttribute(attn_k, cudaFuncAttributeMaxDynamicSharedMemorySize,
                       ATTN_SMEM_BYTES);

  dim3 blk(256);
  // Q projection: [8192,2048] = x @ Wq + bq   -> g_qbuf
  gemm_q_k<<<dim3(16, 64), blk>>>(x, Wq, bq);
  // K,V projections fused: [512,2048] = ctx @ {Wk,Wv} + {bk,bv} -> g_kbuf/g_vbuf
  gemm_kv_k<<<dim3(16, 4, 2), blk>>>(ctx, Wk, bk, Wv, bv);
  // RMSNorm q, k (in place)
  rmsnorm_k<<<L_Q, 256>>>(0, gq);
  rmsnorm_k<<<S_CTX, 256>>>(1, gk);
  // Attention: g_qbuf,g_kbuf,g_vbuf -> g_abuf
  attn_k<<<dim3(L_Q / 64, N_HEADS), blk, ATTN_SMEM_BYTES>>>();
  // Output projection -> d_out
  gemm_o_k<<<dim3(16, 64), blk>>>(Wo, bo, out);
}

// round 4
// speedup vs baseline: 1.0888x; 1.0888x over previous
#include <cuda_runtime.h>
#include <cstdint>

#define L_Q 8192
#define D_MODEL 2048
#define S_CTX 512
#define D_CTX 4096
#define N_HEADS 16
#define D_HEAD 128

// Scratch (allocation-free rule: __device__ globals)
__device__ float g_qbuf[(size_t)L_Q * D_MODEL];
__device__ float g_kbuf[(size_t)S_CTX * D_MODEL];
__device__ float g_vbuf[(size_t)S_CTX * D_MODEL];
__device__ float g_abuf[(size_t)L_Q * D_MODEL];

__device__ __forceinline__ uint32_t f2tf(float f) {
  uint32_t u; asm("cvt.rna.tf32.f32 %0, %1;" : "=r"(u) : "f"(f)); return u;
}

__device__ __forceinline__ void mma_tf32(float c[4], const uint32_t a[4], const uint32_t b[2]) {
  asm("mma.sync.aligned.m16n8k8.row.col.f32.tf32.tf32.f32 "
      "{%0,%1,%2,%3}, {%4,%5,%6,%7}, {%8,%9}, {%0,%1,%2,%3};"
      : "+f"(c[0]), "+f"(c[1]), "+f"(c[2]), "+f"(c[3])
      : "r"(a[0]), "r"(a[1]), "r"(a[2]), "r"(a[3]), "r"(b[0]), "r"(b[1]));
}

__device__ __forceinline__ void cp16(float* smem_dst, const float* gsrc) {
  uint32_t s = (uint32_t)__cvta_generic_to_shared(smem_dst);
  asm volatile("cp.async.cg.shared.global [%0], [%1], 16;" :: "r"(s), "l"(gsrc));
}

// ---------------------------------------------------------------------------
// GEMM: C[M,N] = A[M,K] @ B[K,N] + bias.
// Block 128x128x32, 128 threads, warp tile 64x64 (2x2 warps),
// 3-stage cp.async pipeline, fp32 in smem, tf32 cvt at fragment load.
// Requires M%128==0, N%128==0, K%32==0.
// ---------------------------------------------------------------------------
#define BM 128
#define BN 128
#define BK 32
#define STAGES 3
#define GT 128
#define AS_LD 36            // 36%32==4 -> conflict-free A frags
#define BS_LD 136           // 136%32==8 -> conflict-free B frags
#define A_STAGE (BM * AS_LD)            // 4608 floats
#define B_STAGE (BK * BS_LD)            // 4352 floats
#define STAGE_ELEMS (A_STAGE + B_STAGE) // 8960 floats
#define GEMM_SMEM_BYTES (STAGE_ELEMS * STAGES * 4)  // 107,520 B

__device__ __forceinline__ void gemm_body(
    const float* __restrict__ A, const float* __restrict__ B,
    const float* __restrict__ bias, float* __restrict__ C,
    int M, int N, int K, int bm, int bn)
{
  extern __shared__ float smemf[];
  const int tid = threadIdx.x;
  const int lane = tid & 31, warp = tid >> 5;
  const int g = lane >> 2, tig = lane & 3;
  const int wm = (warp >> 1) * 64, wn = (warp & 1) * 64;
  const int m0 = bm * BM, n0 = bn * BN;
  const int nk = K / BK;

  float acc[4][8][4];
  #pragma unroll
  for (int mi = 0; mi < 4; mi++)
    #pragma unroll
    for (int ni = 0; ni < 8; ni++)
      #pragma unroll
      for (int e = 0; e < 4; e++) acc[mi][ni][e] = 0.f;

  // --- async stage issue ---
  auto issue = [&](int kc) {
    float* As = smemf + (kc % STAGES) * STAGE_ELEMS;
    float* Bs = As + A_STAGE;
    const int k0 = kc * BK;
    #pragma unroll
    for (int i = 0; i < 8; i++) {
      int idx = tid + i * GT;
      int row = idx >> 3, c4 = (idx & 7) << 2;
      cp16(&As[row * AS_LD + c4], &A[(size_t)(m0 + row) * K + k0 + c4]);
    }
    #pragma unroll
    for (int i = 0; i < 8; i++) {
      int idx = tid + i * GT;
      int row = idx >> 5, c4 = (idx & 31) << 2;
      cp16(&Bs[row * BS_LD + c4], &B[(size_t)(k0 + row) * N + n0 + c4]);
    }
    asm volatile("cp.async.commit_group;");
  };

  issue(0);
  if (nk > 1) issue(1);

  #pragma unroll 1
  for (int kc = 0; kc < nk; kc++) {
    if (kc + 1 < nk) asm volatile("cp.async.wait_group 1;");
    else             asm volatile("cp.async.wait_group 0;");
    __syncthreads();
    if (kc + 2 < nk) issue(kc + 2);

    const float* As = smemf + (kc % STAGES) * STAGE_ELEMS;
    const float* Bs = As + A_STAGE;

    #pragma unroll
    for (int ks = 0; ks < 4; ks++) {
      uint32_t af[4][4], bf[8][2];
      #pragma unroll
      for (int mi = 0; mi < 4; mi++) {
        int base = (wm + mi * 16 + g) * AS_LD + ks * 8 + tig;
        af[mi][0] = f2tf(As[base]);
        af[mi][1] = f2tf(As[base + 8 * AS_LD]);
        af[mi][2] = f2tf(As[base + 4]);
        af[mi][3] = f2tf(As[base + 8 * AS_LD + 4]);
      }
      #pragma unroll
      for (int ni = 0; ni < 8; ni++) {
        int col = wn + ni * 8 + g;
        bf[ni][0] = f2tf(Bs[(ks * 8 + tig) * BS_LD + col]);
        bf[ni][1] = f2tf(Bs[(ks * 8 + tig + 4) * BS_LD + col]);
      }
      #pragma unroll
      for (int mi = 0; mi < 4; mi++)
        #pragma unroll
        for (int ni = 0; ni < 8; ni++)
          mma_tf32(acc[mi][ni], af[mi], bf[ni]);
    }
    // no trailing sync: the next iteration's top sync protects buffer reuse
  }

  // epilogue: +bias, write fp32
  #pragma unroll
  for (int mi = 0; mi < 4; mi++) {
    int r = m0 + wm + mi * 16 + g;
    #pragma unroll
    for (int ni = 0; ni < 8; ni++) {
      int c = n0 + wn + ni * 8 + 2 * tig;
      float b0 = bias[c], b1 = bias[c + 1];
      *(float2*)&C[(size_t)r * N + c] =
          make_float2(acc[mi][ni][0] + b0, acc[mi][ni][1] + b1);
      *(float2*)&C[(size_t)(r + 8) * N + c] =
          make_float2(acc[mi][ni][2] + b0, acc[mi][ni][3] + b1);
    }
  }
}

// Q projection -> g_qbuf
__global__ __launch_bounds__(GT) void gemm_q_k(
    const float* __restrict__ A, const float* __restrict__ B,
    const float* __restrict__ bias)
{
  gemm_body(A, B, bias, g_qbuf, L_Q, D_MODEL, D_MODEL, blockIdx.y, blockIdx.x);
}

// O projection: g_abuf -> harness output
__global__ __launch_bounds__(GT) void gemm_o_k(
    const float* __restrict__ B, const float* __restrict__ bias,
    float* __restrict__ C)
{
  gemm_body(g_abuf, B, bias, C, L_Q, D_MODEL, D_MODEL, blockIdx.y, blockIdx.x);
}

// K,V projections fused over blockIdx.z
__global__ __launch_bounds__(GT) void gemm_kv_k(
    const float* __restrict__ A,
    const float* __restrict__ Bk, const float* __restrict__ bk,
    const float* __restrict__ Bv, const float* __restrict__ bv)
{
  const float* B  = blockIdx.z ? Bv : Bk;
  const float* bb = blockIdx.z ? bv : bk;
  float*       C  = blockIdx.z ? g_vbuf : g_kbuf;
  gemm_body(A, B, bb, C, S_CTX, D_MODEL, D_CTX, blockIdx.y, blockIdx.x);
}

// ---------------------------------------------------------------------------
// RMSNorm in place over rows of 2048.  One block per row; rows [0,L_Q) are
// g_qbuf (weight gq), rows [L_Q, L_Q+S_CTX) are g_kbuf (weight gk).
// ---------------------------------------------------------------------------
__global__ __launch_bounds__(256, 1) void rmsnorm_k(const float* __restrict__ gwq,
                                                    const float* __restrict__ gwk)
{
  int row = blockIdx.x;
  float* data;
  const float* gw;
  if (row < L_Q) { data = g_qbuf; gw = gwq; }
  else           { data = g_kbuf; gw = gwk; row -= L_Q; }

  const int tid = threadIdx.x;
  const int lane = tid & 31, warp = tid >> 5;
  float4* p = (float4*)(data + (size_t)row * D_MODEL);
  float4 v0 = p[tid], v1 = p[tid + 256];
  float s = v0.x * v0.x + v0.y * v0.y + v0.z * v0.z + v0.w * v0.w
          + v1.x * v1.x + v1.y * v1.y + v1.z * v1.z + v1.w * v1.w;
  #pragma unroll
  for (int o = 16; o; o >>= 1) s += __shfl_xor_sync(0xffffffffu, s, o);
  __shared__ float ws[8];
  if (lane == 0) ws[warp] = s;
  __syncthreads();
  float tot = ws[0] + ws[1] + ws[2] + ws[3] + ws[4] + ws[5] + ws[6] + ws[7];
  float scl = rsqrtf(tot * (1.0f / D_MODEL) + 1e-6f);
  const float4* gp = (const float4*)gw;
  float4 g0 = gp[tid], g1 = gp[tid + 256];
  v0.x *= scl * g0.x; v0.y *= scl * g0.y; v0.z *= scl * g0.z; v0.w *= scl * g0.w;
  v1.x *= scl * g1.x; v1.y *= scl * g1.y; v1.z *= scl * g1.z; v1.w *= scl * g1.w;
  p[tid] = v0; p[tid + 256] = v1;
}

// ---------------------------------------------------------------------------
// Attention: one block = (head, 64 q rows).  Materialize 64x512 scores in
// smem via tf32 MMA, smem softmax (unnormalized; 1/sum folded into PV
// epilogue), then P @ V via tf32 MMA.  256 threads.
// ---------------------------------------------------------------------------
#define ATTN_SMEM_BYTES ((64 * 132 + 64 * 136 + 64 * 516 + 64) * 4)

__global__ __launch_bounds__(256, 1) void attn_k()
{
  extern __shared__ uint32_t sm[];
  uint32_t* qs  = sm;                     // [64][132]
  uint32_t* kvs = sm + 64 * 132;          // [64][132] as K / [64][136] as V
  float*    sc  = (float*)(sm + 64 * 132 + 64 * 136);  // [64][516]
  float*    rinv = sc + 64 * 516;         // [64]

  const float* __restrict__ q  = g_qbuf;
  const float* __restrict__ kk = g_kbuf;
  const float* __restrict__ vv = g_vbuf;
  float* __restrict__ o = g_abuf;

  const int tid = threadIdx.x;
  const int lane = tid & 31, warp = tid >> 5;
  const int g = lane >> 2, tig = lane & 3;
  const int h = blockIdx.y;
  const int qb = blockIdx.x * 64;
  const size_t hoff = (size_t)h * D_HEAD;

  #pragma unroll
  for (int i = 0; i < 8; i++) {
    int idx = tid + i * 256;
    int row = idx >> 5, c4 = (idx & 31) << 2;
    float4 vq = *(const float4*)&q[(size_t)(qb + row) * D_MODEL + hoff + c4];
    uint32_t* d = &qs[row * 132 + c4];
    d[0] = f2tf(vq.x); d[1] = f2tf(vq.y); d[2] = f2tf(vq.z); d[3] = f2tf(vq.w);
  }

  // ---- Phase A: scores = Q K^T ----
  const int wmA = (warp >> 2) * 32, wnA = (warp & 3) * 16;
  #pragma unroll 1
  for (int st = 0; st < 8; st++) {
    __syncthreads();
    #pragma unroll
    for (int i = 0; i < 8; i++) {
      int idx = tid + i * 256;
      int row = idx >> 5, c4 = (idx & 31) << 2;
      float4 vk = *(const float4*)&kk[(size_t)(st * 64 + row) * D_MODEL + hoff + c4];
      uint32_t* d = &kvs[row * 132 + c4];
      d[0] = f2tf(vk.x); d[1] = f2tf(vk.y); d[2] = f2tf(vk.z); d[3] = f2tf(vk.w);
    }
    __syncthreads();

    float acc[2][2][4];
    #pragma unroll
    for (int mi = 0; mi < 2; mi++)
      #pragma unroll
      for (int ni = 0; ni < 2; ni++)
        #pragma unroll
        for (int e = 0; e < 4; e++) acc[mi][ni][e] = 0.f;

    #pragma unroll
    for (int ks = 0; ks < 16; ks++) {
      uint32_t af[2][4], bf[2][2];
      #pragma unroll
      for (int mi = 0; mi < 2; mi++) {
        int base = (wmA + mi * 16 + g) * 132 + ks * 8 + tig;
        af[mi][0] = qs[base];
        af[mi][1] = qs[base + 8 * 132];
        af[mi][2] = qs[base + 4];
        af[mi][3] = qs[base + 8 * 132 + 4];
      }
      #pragma unroll
      for (int ni = 0; ni < 2; ni++) {
        int col = wnA + ni * 8 + g;
        bf[ni][0] = kvs[col * 132 + ks * 8 + tig];
        bf[ni][1] = kvs[col * 132 + ks * 8 + tig + 4];
      }
      #pragma unroll
      for (int mi = 0; mi < 2; mi++)
        #pragma unroll
        for (int ni = 0; ni < 2; ni++)
          mma_tf32(acc[mi][ni], af[mi], bf[ni]);
    }
    #pragma unroll
    for (int mi = 0; mi < 2; mi++) {
      int r = wmA + mi * 16 + g;
      #pragma unroll
      for (int ni = 0; ni < 2; ni++) {
        int c = st * 64 + wnA + ni * 8 + 2 * tig;
        *(float2*)&sc[r * 516 + c]       = make_float2(acc[mi][ni][0], acc[mi][ni][1]);
        *(float2*)&sc[(r + 8) * 516 + c] = make_float2(acc[mi][ni][2], acc[mi][ni][3]);
      }
    }
  }
  __syncthreads();

  // ---- Softmax ----
  const float sscale = 0.08838834764831845f;  // 1/sqrt(128)
  #pragma unroll 1
  for (int j = 0; j < 8; j++) {
    int r = warp * 8 + j;
    float* row = &sc[r * 516];
    float mx = -1e30f;
    #pragma unroll
    for (int c = lane; c < 512; c += 32) mx = fmaxf(mx, row[c]);
    #pragma unroll
    for (int off = 16; off; off >>= 1) mx = fmaxf(mx, __shfl_xor_sync(0xffffffffu, mx, off));
    float sum = 0.f;
    #pragma unroll
    for (int c = lane; c < 512; c += 32) {
      float e = __expf((row[c] - mx) * sscale);
      sum += e;
      row[c] = __uint_as_float(f2tf(e));
    }
    #pragma unroll
    for (int off = 16; off; off >>= 1) sum += __shfl_xor_sync(0xffffffffu, sum, off);
    if (lane == 0) rinv[r] = 1.0f / sum;
  }
  __syncthreads();

  // ---- Phase B: out = P @ V ----
  const int wmB = (warp >> 2) * 32, wnB = (warp & 3) * 32;
  float co[2][4][4];
  #pragma unroll
  for (int mi = 0; mi < 2; mi++)
    #pragma unroll
    for (int ni = 0; ni < 4; ni++)
      #pragma unroll
      for (int e = 0; e < 4; e++) co[mi][ni][e] = 0.f;

  #pragma unroll 1
  for (int sv = 0; sv < 8; sv++) {
    __syncthreads();
    #pragma unroll
    for (int i = 0; i < 8; i++) {
      int idx = tid + i * 256;
      int row = idx >> 5, c4 = (idx & 31) << 2;
      float4 vw = *(const float4*)&vv[(size_t)(sv * 64 + row) * D_MODEL + hoff + c4];
      uint32_t* d = &kvs[row * 136 + c4];
      d[0] = f2tf(vw.x); d[1] = f2tf(vw.y); d[2] = f2tf(vw.z); d[3] = f2tf(vw.w);
    }
    __syncthreads();

    #pragma unroll
    for (int ks = 0; ks < 8; ks++) {
      uint32_t af[2][4], bf[4][2];
      #pragma unroll
      for (int mi = 0; mi < 2; mi++) {
        int base = (wmB + mi * 16 + g) * 516 + sv * 64 + ks * 8 + tig;
        af[mi][0] = __float_as_uint(sc[base]);
        af[mi][1] = __float_as_uint(sc[base + 8 * 516]);
        af[mi][2] = __float_as_uint(sc[base + 4]);
        af[mi][3] = __float_as_uint(sc[base + 8 * 516 + 4]);
      }
      #pragma unroll
      for (int ni = 0; ni < 4; ni++) {
        int col = wnB + ni * 8 + g;
        bf[ni][0] = kvs[(ks * 8 + tig) * 136 + col];
        bf[ni][1] = kvs[(ks * 8 + tig + 4) * 136 + col];
      }
      #pragma unroll
      for (int mi = 0; mi < 2; mi++)
        #pragma unroll
        for (int ni = 0; ni < 4; ni++)
          mma_tf32(co[mi][ni], af[mi], bf[ni]);
    }
  }

  #pragma unroll
  for (int mi = 0; mi < 2; mi++) {
    int rl = wmB + mi * 16 + g;
    float r0 = rinv[rl], r1 = rinv[rl + 8];
    #pragma unroll
    for (int ni = 0; ni < 4; ni++) {
      int c = wnB + ni * 8 + 2 * tig;
      *(float2*)&o[(size_t)(qb + rl) * D_MODEL + hoff + c] =
          make_float2(co[mi][ni][0] * r0, co[mi][ni][1] * r0);
      *(float2*)&o[(size_t)(qb + rl + 8) * D_MODEL + hoff + c] =
          make_float2(co[mi][ni][2] * r1, co[mi][ni][3] * r1);
    }
  }
}

// ---------------------------------------------------------------------------
extern "C" void kernel_launch(void* const* d_in, const int* in_sizes, int n_in,
                              void* d_out, int out_size)
{
  const float* x   = (const float*)d_in[0];
  const float* ctx = (const float*)d_in[1];
  const float* Wq  = (const float*)d_in[2];
  const float* bq  = (const float*)d_in[3];
  const float* Wk  = (const float*)d_in[4];
  const float* bk  = (const float*)d_in[5];
  const float* Wv  = (const float*)d_in[6];
  const float* bv  = (const float*)d_in[7];
  const float* Wo  = (const float*)d_in[8];
  const float* bo  = (const float*)d_in[9];
  const float* gq  = (const float*)d_in[10];
  const float* gk  = (const float*)d_in[11];
  float* out = (float*)d_out;

  cudaFuncSetAttribute(attn_k, cudaFuncAttributeMaxDynamicSharedMemorySize,
                       ATTN_SMEM_BYTES);
  cudaFuncSetAttribute(gemm_q_k, cudaFuncAttributeMaxDynamicSharedMemorySize,
                       GEMM_SMEM_BYTES);
  cudaFuncSetAttribute(gemm_o_k, cudaFuncAttributeMaxDynamicSharedMemorySize,
                       GEMM_SMEM_BYTES);
  cudaFuncSetAttribute(gemm_kv_k, cudaFuncAttributeMaxDynamicSharedMemorySize,
                       GEMM_SMEM_BYTES);

  dim3 blk(GT);
  // Q projection: [8192,2048] = x @ Wq + bq   -> g_qbuf
  gemm_q_k<<<dim3(16, 64), blk, GEMM_SMEM_BYTES>>>(x, Wq, bq);
  // K,V projections fused: [512,2048] = ctx @ {Wk,Wv} + {bk,bv} -> g_kbuf/g_vbuf
  gemm_kv_k<<<dim3(16, 4, 2), blk, GEMM_SMEM_BYTES>>>(ctx, Wk, bk, Wv, bv);
  // RMSNorm q and k in one launch (rows 0..8191 -> q, 8192..8703 -> k)
  rmsnorm_k<<<L_Q + S_CTX, 256>>>(gq, gk);
  // Attention: g_qbuf,g_kbuf,g_vbuf -> g_abuf
  attn_k<<<dim3(L_Q / 64, N_HEADS), 256, ATTN_SMEM_BYTES>>>();
  // Output projection -> d_out
  gemm_o_k<<<dim3(16, 64), blk, GEMM_SMEM_BYTES>>>(Wo, bo, out);
}